// round 11
// baseline (speedup 1.0000x reference)
#include <cuda_runtime.h>
#include <cuda_fp16.h>
#include <math.h>

#define DIN   128
#define DOUT  128
#define NB    2048
#define NU    20000
#define NMC   4
#define EPB   32
#define RES   0.9f

#define NBN   64            // 8192/128 blocks for neigh GEMM
#define LDA2  68            // A smem row stride in half2 words
#define LDWH  136           // W smem row stride in halfs (68 half2 words)

// Scratch
__device__ __half g_embed_h[NU * DIN];        // [20000,128] fp16 agg_table[unique_ids]
__device__ __half g_neigh_h[NB * NMC * DIN];  // [8192,128] fp16 pre-agg neighbors
__device__ float  g_neigh_v[NB * NMC * DOUT]; // [8192,128] neigh @ Wv_agg
__device__ float  g_agg_all[NB * 3 * DOUT];   // [2048,384] = self_agg | K0 | Q0
__device__ float  g_ff_all [NB * 3 * DOUT];   // [2048,384] = self_ff  | K1 | Q1

__device__ __forceinline__ void mma_f16(float* c, const unsigned* a,
                                        unsigned b0, unsigned b1) {
    asm volatile(
        "mma.sync.aligned.m16n8k16.row.col.f32.f16.f16.f32 "
        "{%0,%1,%2,%3}, {%4,%5,%6,%7}, {%8,%9}, {%0,%1,%2,%3};\n"
        : "+f"(c[0]), "+f"(c[1]), "+f"(c[2]), "+f"(c[3])
        : "r"(a[0]), "r"(a[1]), "r"(a[2]), "r"(a[3]), "r"(b0), "r"(b1));
}

// ---------------------------------------------------------------------------
// embed16: g_embed_h[r] = fp16(agg_table[unique_ids[r]]); warp per row.
// ---------------------------------------------------------------------------
__global__ __launch_bounds__(256) void embed16_kernel(
    const int* __restrict__ unique_ids, const float* __restrict__ agg_table)
{
    const int lane = threadIdx.x & 31;
    const int row = blockIdx.x * 8 + (threadIdx.x >> 5);
    const int uid = __ldg(unique_ids + row);
    float4 v = __ldcg((const float4*)(agg_table + (long)uid * DIN + lane * 4));
    __half2 h01 = __floats2half2_rn(v.x, v.y);
    __half2 h23 = __floats2half2_rn(v.z, v.w);
    *(uint2*)(g_embed_h + (long)row * DIN + lane * 4) =
        make_uint2(*(unsigned*)&h01, *(unsigned*)&h23);
}

// ---------------------------------------------------------------------------
// Aggregate: warp = (node, layer). Dedup (set semantics), __fns slot-compact,
// batched mean of fp16 embed rows (256B/edge, no indirection), store fp16.
// ---------------------------------------------------------------------------
__global__ __launch_bounds__(256) void aggregate_kernel(
    const int* __restrict__ layer_idx, const int* __restrict__ col_idx)
{
    const int lane = threadIdx.x & 31;
    const int warp = threadIdx.x >> 5;          // 0..7
    const int n = blockIdx.x * 2 + (warp >> 2);
    const int m = warp & 3;

    int lay = __ldg(layer_idx + n * EPB + lane);
    int col = __ldg(col_idx + n * EPB + lane);
    int key = (lay << 15) | col;                // dedup on (lay, col) pairs
    unsigned mm = __match_any_sync(0xffffffffu, key);
    bool valid = ((mm & ((1u << lane) - 1u)) == 0u);
    unsigned bits = __ballot_sync(0xffffffffu, valid && (lay == m));
    const int cm = __popc(bits);

    int pos = (int)__fns(bits, 0, lane + 1);
    int epos = (pos < 0 || pos > 31) ? 0 : pos;
    int slotcol = __shfl_sync(0xffffffffu, col, epos);  // col for slot=lane

    float acc0 = 0.f, acc1 = 0.f, acc2 = 0.f, acc3 = 0.f;
    #pragma unroll
    for (int b = 0; b < 4; b++) {
        if (cm > 8 * b) {                        // warp-uniform
            uint2 v[8]; float wt[8];
            #pragma unroll
            for (int j = 0; j < 8; j++) {
                int slot = 8 * b + j;
                int ce = __shfl_sync(0xffffffffu, slotcol, slot);
                wt[j] = (slot < cm) ? 1.f : 0.f;
                v[j] = *(const uint2*)(g_embed_h + (long)ce * DIN + lane * 4);
            }
            #pragma unroll
            for (int j = 0; j < 8; j++) {
                float2 f01 = __half22float2(*(__half2*)&v[j].x);
                float2 f23 = __half22float2(*(__half2*)&v[j].y);
                acc0 = fmaf(f01.x, wt[j], acc0);
                acc1 = fmaf(f01.y, wt[j], acc1);
                acc2 = fmaf(f23.x, wt[j], acc2);
                acc3 = fmaf(f23.y, wt[j], acc3);
            }
        }
    }
    float inv = __fdividef(1.f, fmaxf((float)cm, 1.f));
    __half2 h01 = __floats2half2_rn(acc0 * inv, acc1 * inv);
    __half2 h23 = __floats2half2_rn(acc2 * inv, acc3 * inv);
    *(uint2*)(g_neigh_h + (long)(n * NMC + m) * DIN + lane * 4) =
        make_uint2(*(unsigned*)&h01, *(unsigned*)&h23);
}

// ---------------------------------------------------------------------------
// GEMM, fp16 mma (m16n8k16), fp32 accumulate. job_base selects the job range:
//   bx_eff <  64: g_neigh_v = g_neigh_h @ Wv_agg (contiguous fp16 A)
//   bx_eff >= 64: self features (gathered) @ {Wv|Wk|Wq}
// ---------------------------------------------------------------------------
__global__ __launch_bounds__(128, 2) void gemm_tc_kernel(
    const float* __restrict__ agg_table, const float* __restrict__ ff_table,
    const int* __restrict__ nodes,
    const float* __restrict__ Wv_agg, const float* __restrict__ Wv_ff,
    const float* __restrict__ Wk,     const float* __restrict__ Wq,
    int job_base)
{
    extern __shared__ unsigned smem[];
    unsigned* As = smem;                    // [128][LDA2] half2 words
    unsigned* Ws = smem + 128 * LDA2;       // [128][LDWH/2] half2 words

    const float* table; const float* W; float* out;
    int M, ldout, col0, row0, neigh_job;
    int bx = blockIdx.x + job_base;
    if (bx < NBN) {
        neigh_job = 1; table = agg_table; W = Wv_agg; out = g_neigh_v;
        M = NB * NMC; ldout = DOUT; col0 = 0; row0 = bx * 128;
    } else {
        neigh_job = 0;
        int b = bx - NBN;
        int grp = b / 48;            // 0: agg, 1: ff
        int b2 = b % 48;
        int wsel = b2 / 16, mb = b2 % 16;
        table = grp ? ff_table : agg_table;
        W = (wsel == 0) ? (grp ? Wv_ff : Wv_agg) : (wsel == 1 ? Wk : Wq);
        out = grp ? g_ff_all : g_agg_all;
        M = NB; ldout = 3 * DOUT; col0 = wsel * 128; row0 = mb * 128;
    }

    const int lane = threadIdx.x & 31;
    const int warp = threadIdx.x >> 5;
    const int g  = lane >> 2;
    const int tg = lane & 3;
    const int wr0 = warp * 32;

    if (neigh_job) {
        #pragma unroll
        for (int i = 0; i < 32; i++) {
            int row = wr0 + i;
            uint2 x = __ldcg((const uint2*)(g_neigh_h + (long)(row0 + row) * DIN + lane * 4));
            *(uint2*)(As + row * LDA2 + lane * 2) = x;
        }
    } else {
        int myrow = row0 + wr0 + lane;
        myrow = (myrow < M) ? myrow : (M - 1);
        const int myidx = __ldg(nodes + myrow);
        #pragma unroll
        for (int e = 0; e < 32; e++) {
            int ridx = __shfl_sync(0xffffffffu, myidx, e);
            float4 x = __ldcg((const float4*)(table + (long)ridx * DIN + lane * 4));
            __half2 h01 = __floats2half2_rn(x.x, x.y);
            __half2 h23 = __floats2half2_rn(x.z, x.w);
            *(uint2*)(As + (wr0 + e) * LDA2 + lane * 2) =
                make_uint2(*(unsigned*)&h01, *(unsigned*)&h23);
        }
    }

    // stage W rows [wr0, wr0+32)
    #pragma unroll
    for (int i = 0; i < 32; i++) {
        int row = wr0 + i;
        float4 v = *(const float4*)(W + row * 128 + lane * 4);
        __half2 h01 = __floats2half2_rn(v.x, v.y);
        __half2 h23 = __floats2half2_rn(v.z, v.w);
        *(uint2*)(Ws + row * (LDWH / 2) + lane * 2) =
            make_uint2(*(unsigned*)&h01, *(unsigned*)&h23);
    }
    __syncthreads();

    unsigned ws_s;
    {
        unsigned long long p;
        asm("cvta.to.shared.u64 %0, %1;" : "=l"(p) : "l"((const void*)Ws));
        ws_s = (unsigned)p;
    }

    float acc[2][16][4];
    #pragma unroll
    for (int mt = 0; mt < 2; mt++)
        #pragma unroll
        for (int j = 0; j < 16; j++)
            #pragma unroll
            for (int q = 0; q < 4; q++) acc[mt][j][q] = 0.f;

    const int lgrp = lane >> 3;
    const int lrow = lane & 7;
    const int kofs = (lgrp & 1) * 8 + lrow;
    const int nofs = (lgrp >> 1) * 8;

    #pragma unroll
    for (int kk = 0; kk < 8; kk++) {     // k16 chunks
        unsigned a[2][4];
        #pragma unroll
        for (int mt = 0; mt < 2; mt++) {
            const unsigned* ab = As + (wr0 + mt * 16) * LDA2 + kk * 8;
            a[mt][0] = ab[g * LDA2 + tg];
            a[mt][1] = ab[(g + 8) * LDA2 + tg];
            a[mt][2] = ab[g * LDA2 + 4 + tg];
            a[mt][3] = ab[(g + 8) * LDA2 + 4 + tg];
        }
        unsigned rowaddr = ws_s + ((kk * 16 + kofs) * LDWH + nofs) * 2;
        #pragma unroll
        for (int jj = 0; jj < 8; jj++) { // n16 chunks
            unsigned b0, b1, b2, b3;
            asm volatile(
                "ldmatrix.sync.aligned.m8n8.x4.trans.shared.b16 "
                "{%0,%1,%2,%3}, [%4];"
                : "=r"(b0), "=r"(b1), "=r"(b2), "=r"(b3)
                : "r"(rowaddr + jj * 32));
            mma_f16(acc[0][2 * jj],     a[0], b0, b1);
            mma_f16(acc[0][2 * jj + 1], a[0], b2, b3);
            mma_f16(acc[1][2 * jj],     a[1], b0, b1);
            mma_f16(acc[1][2 * jj + 1], a[1], b2, b3);
        }
    }

    // epilogue
    #pragma unroll
    for (int mt = 0; mt < 2; mt++) {
        int rbase = row0 + wr0 + mt * 16;
        #pragma unroll
        for (int j = 0; j < 16; j++) {
            int c = col0 + j * 8 + 2 * tg;
            int r0g = rbase + g;
            *(float2*)(out + (long)r0g * ldout + c) =
                make_float2(acc[mt][j][0], acc[mt][j][1]);
            int r1g = rbase + 8 + g;
            *(float2*)(out + (long)r1g * ldout + c) =
                make_float2(acc[mt][j][2], acc[mt][j][3]);
        }
    }
}

// ---------------------------------------------------------------------------
// Finalize: warp-per-node (4/block), gather-free.
// ---------------------------------------------------------------------------
#define NRED 14
__global__ __launch_bounds__(128) void finalize_kernel(
    const float* __restrict__ mu_w, float* __restrict__ out)
{
    const int lane = threadIdx.x & 31;
    const int warp = threadIdx.x >> 5;
    const int n = blockIdx.x * 4 + warp;

    float4 nb[NMC];
    #pragma unroll
    for (int m = 0; m < NMC; m++)
        nb[m] = *(const float4*)(g_neigh_v + (long)(n * NMC + m) * DOUT + lane * 4);

    const float* ar = g_agg_all + (long)n * (3 * DOUT);
    const float* fr = g_ff_all  + (long)n * (3 * DOUT);
    float4 sa  = *(const float4*)(ar + lane * 4);
    float4 k0  = *(const float4*)(ar + DOUT + lane * 4);
    float4 q0  = *(const float4*)(ar + 2 * DOUT + lane * 4);
    float4 sff = *(const float4*)(fr + lane * 4);
    float4 k1  = *(const float4*)(fr + DOUT + lane * 4);
    float4 q1  = *(const float4*)(fr + 2 * DOUT + lane * 4);
    float4 mu0 = *(const float4*)(mu_w + lane * 4);
    float4 mu1 = *(const float4*)(mu_w + DOUT + lane * 4);

    #define DOT4(a, b) ((a).x*(b).x + (a).y*(b).y + (a).z*(b).z + (a).w*(b).w)
    float p[NRED];
    p[0]  = DOT4(sa, sa);       p[1]  = DOT4(sa, mu0);
    p[2]  = DOT4(nb[0], nb[0]); p[3]  = DOT4(nb[0], mu1);
    p[4]  = DOT4(nb[1], nb[1]); p[5]  = DOT4(nb[1], mu1);
    p[6]  = DOT4(nb[2], nb[2]); p[7]  = DOT4(nb[2], mu1);
    p[8]  = DOT4(nb[3], nb[3]); p[9]  = DOT4(nb[3], mu1);
    p[10] = DOT4(k0, q0); p[11] = DOT4(k0, q1);
    p[12] = DOT4(k1, q0); p[13] = DOT4(k1, q1);

    #pragma unroll
    for (int o = 16; o > 0; o >>= 1)
        #pragma unroll
        for (int i = 0; i < NRED; i++)
            p[i] += __shfl_xor_sync(0xffffffffu, p[i], o);

    float logit[NMC];
    #pragma unroll
    for (int m = 0; m < NMC; m++)
        logit[m] = (p[1] + p[3 + 2 * m]) * __frsqrt_rn(fmaxf(p[0] + p[2 + 2 * m], 1e-24f));
    float mx = fmaxf(fmaxf(logit[0], logit[1]), fmaxf(logit[2], logit[3]));
    float ex[NMC], es = 0.f;
    #pragma unroll
    for (int m = 0; m < NMC; m++) { ex[m] = __expf(logit[m] - mx); es += ex[m]; }
    float ies = __fdividef(1.f, es);
    float4 nsum = make_float4(0.f, 0.f, 0.f, 0.f);
    #pragma unroll
    for (int m = 0; m < NMC; m++) {
        float c = ex[m] * ies;
        nsum.x = fmaf(c, nb[m].x, nsum.x); nsum.y = fmaf(c, nb[m].y, nsum.y);
        nsum.z = fmaf(c, nb[m].z, nsum.z); nsum.w = fmaf(c, nb[m].w, nsum.w);
    }
    float4 va = make_float4(0.5f * (sa.x + nsum.x), 0.5f * (sa.y + nsum.y),
                            0.5f * (sa.z + nsum.z), 0.5f * (sa.w + nsum.w));

    float s00 = p[10] * (1.f / 128.f), s01 = p[11] * (1.f / 128.f);
    float s10 = p[12] * (1.f / 128.f), s11 = p[13] * (1.f / 128.f);
    float m0 = fmaxf(s00, s01), m1 = fmaxf(s10, s11);
    float e00 = __expf(s00 - m0), e01 = __expf(s01 - m0);
    float e10 = __expf(s10 - m1), e11 = __expf(s11 - m1);
    float i0 = __fdividef(1.f, e00 + e01);
    float i1 = __fdividef(1.f, e10 + e11);
    float w00 = e00 * i0, w01 = e01 * i0;
    float w10 = e10 * i1, w11 = e11 * i1;

    float4 o0, o1;
    #define FIN(comp) do { \
        float nv0 = w00 * va.comp + w01 * sff.comp; \
        float nv1 = w10 * va.comp + w11 * sff.comp; \
        float a0 = RES * va.comp  + (1.f - RES) * nv0; \
        float a1 = RES * sff.comp + (1.f - RES) * nv1; \
        o0.comp = (a0 > 0.f) ? a0 : (__expf(a0) - 1.f); \
        o1.comp = (a1 > 0.f) ? a1 : (__expf(a1) - 1.f); \
    } while (0)
    FIN(x); FIN(y); FIN(z); FIN(w);

    *(float4*)(out + (long)n * DOUT + lane * 4) = o0;
    *(float4*)(out + (long)NB * DOUT + (long)n * DOUT + lane * 4) = o1;
}

// ---------------------------------------------------------------------------
extern "C" void kernel_launch(void* const* d_in, const int* in_sizes, int n_in,
                              void* d_out, int out_size)
{
    const int*   nodes      = (const int*)  d_in[0];
    const int*   unique_ids = (const int*)  d_in[1];
    // d_in[2] = row_idx: repeat(arange(B), 32) — implicit
    const int*   layer_idx  = (const int*)  d_in[3];
    const int*   col_idx    = (const int*)  d_in[4];
    const float* agg_table  = (const float*)d_in[5];
    const float* ff_table   = (const float*)d_in[6];
    const float* Wv_agg     = (const float*)d_in[7];
    const float* Wv_ff      = (const float*)d_in[8];
    const float* Wk         = (const float*)d_in[9];
    const float* Wq         = (const float*)d_in[10];
    const float* mu_w       = (const float*)d_in[11];
    float* out = (float*)d_out;

    // Host-side handles, created once on the first (non-capture) call.
    static cudaStream_t s2 = nullptr;
    static cudaEvent_t ev0 = nullptr, ev1 = nullptr;
    if (s2 == nullptr) {
        cudaStreamCreateWithFlags(&s2, cudaStreamNonBlocking);
        cudaEventCreateWithFlags(&ev0, cudaEventDisableTiming);
        cudaEventCreateWithFlags(&ev1, cudaEventDisableTiming);
    }

    const int smem_bytes = (128 * LDA2 + 128 * (LDWH / 2)) * (int)sizeof(unsigned);
    cudaFuncSetAttribute(gemm_tc_kernel,
                         cudaFuncAttributeMaxDynamicSharedMemorySize, smem_bytes);

    // fork: side stream runs embed16 -> aggregate, concurrent with self-GEMM
    cudaEventRecord(ev0, 0);
    cudaStreamWaitEvent(s2, ev0, 0);
    embed16_kernel<<<NU / 8, 256, 0, s2>>>(unique_ids, agg_table);
    aggregate_kernel<<<NB / 2, 256, 0, s2>>>(layer_idx, col_idx);
    cudaEventRecord(ev1, s2);

    // main stream: self-feature GEMM (jobs 64..159)
    gemm_tc_kernel<<<96, 128, smem_bytes>>>(
        agg_table, ff_table, nodes, Wv_agg, Wv_ff, Wk, Wq, NBN);

    // join, then neigh GEMM (jobs 0..63) and finalize
    cudaStreamWaitEvent(0, ev1, 0);
    gemm_tc_kernel<<<NBN, 128, smem_bytes>>>(
        agg_table, ff_table, nodes, Wv_agg, Wv_ff, Wk, Wq, 0);

    finalize_kernel<<<NB / 4, 128>>>(mu_w, out);
}

// round 12
// speedup vs baseline: 1.0025x; 1.0025x over previous
#include <cuda_runtime.h>
#include <cuda_fp16.h>
#include <math.h>

#define DIN   128
#define DOUT  128
#define NB    2048
#define NU    20000
#define NMC   4
#define EPB   32
#define RES   0.9f

#define LDA2  68            // A smem row stride in half2 words (64 rows)
#define LDWH  136           // W smem row stride in halfs
#define LDF   132           // finalize smem row stride (floats)
#define NBS   192           // self-GEMM blocks: 6 jobs x 32 m-blocks (m64)
#define NBE5  5000          // embed16 blocks (4 rows each)

// Scratch
__device__ __half g_embed_h[NU * DIN];        // fp16 agg_table[unique_ids]
__device__ __half g_neigh_h[NB * NMC * DIN];  // fp16 pre-agg neighbors
__device__ float  g_agg_all[NB * 3 * DOUT];   // self_agg | K0 | Q0
__device__ float  g_ff_all [NB * 3 * DOUT];   // self_ff  | K1 | Q1

__device__ __forceinline__ void mma_f16(float* c, const unsigned* a,
                                        unsigned b0, unsigned b1) {
    asm volatile(
        "mma.sync.aligned.m16n8k16.row.col.f32.f16.f16.f32 "
        "{%0,%1,%2,%3}, {%4,%5,%6,%7}, {%8,%9}, {%0,%1,%2,%3};\n"
        : "+f"(c[0]), "+f"(c[1]), "+f"(c[2]), "+f"(c[3])
        : "r"(a[0]), "r"(a[1]), "r"(a[2]), "r"(a[3]), "r"(b0), "r"(b1));
}

// m64 x n128 fp16 GEMM mainloop pieces shared by K1/K3 (warp = m16 x n128)
struct GemmCtx {
    unsigned* As; unsigned* Ws; unsigned ws_s;
    int lane, warp, g, tg, wr0, kofs, nofs;
};

__device__ __forceinline__ void gemm_init(GemmCtx& c, unsigned* smem) {
    c.As = smem;
    c.Ws = smem + 64 * LDA2;
    c.lane = threadIdx.x & 31;
    c.warp = threadIdx.x >> 5;
    c.g = c.lane >> 2; c.tg = c.lane & 3;
    c.wr0 = c.warp * 16;
    int lgrp = c.lane >> 3, lrow = c.lane & 7;
    c.kofs = (lgrp & 1) * 8 + lrow;
    c.nofs = (lgrp >> 1) * 8;
    unsigned long long p;
    asm("cvta.to.shared.u64 %0, %1;" : "=l"(p) : "l"((const void*)c.Ws));
    c.ws_s = (unsigned)p;
}

__device__ __forceinline__ void gemm_stage_w(const GemmCtx& c,
                                             const float* __restrict__ W) {
    #pragma unroll
    for (int i = 0; i < 32; i++) {
        int row = c.warp * 32 + i;
        float4 v = *(const float4*)(W + row * 128 + c.lane * 4);
        __half2 h01 = __floats2half2_rn(v.x, v.y);
        __half2 h23 = __floats2half2_rn(v.z, v.w);
        *(uint2*)(c.Ws + row * (LDWH / 2) + c.lane * 2) =
            make_uint2(*(unsigned*)&h01, *(unsigned*)&h23);
    }
}

__device__ __forceinline__ void gemm_main(const GemmCtx& c, float acc[16][4]) {
    #pragma unroll
    for (int j = 0; j < 16; j++)
        #pragma unroll
        for (int q = 0; q < 4; q++) acc[j][q] = 0.f;
    #pragma unroll
    for (int kk = 0; kk < 8; kk++) {
        const unsigned* ab = c.As + c.wr0 * LDA2 + kk * 8;
        unsigned a[4];
        a[0] = ab[c.g * LDA2 + c.tg];
        a[1] = ab[(c.g + 8) * LDA2 + c.tg];
        a[2] = ab[c.g * LDA2 + 4 + c.tg];
        a[3] = ab[(c.g + 8) * LDA2 + 4 + c.tg];
        unsigned rowaddr = c.ws_s + ((kk * 16 + c.kofs) * LDWH + c.nofs) * 2;
        #pragma unroll
        for (int jj = 0; jj < 8; jj++) {
            unsigned b0, b1, b2, b3;
            asm volatile(
                "ldmatrix.sync.aligned.m8n8.x4.trans.shared.b16 "
                "{%0,%1,%2,%3}, [%4];"
                : "=r"(b0), "=r"(b1), "=r"(b2), "=r"(b3)
                : "r"(rowaddr + jj * 32));
            mma_f16(acc[2 * jj],     a, b0, b1);
            mma_f16(acc[2 * jj + 1], a, b2, b3);
        }
    }
}

// ---------------------------------------------------------------------------
// K1: self-feature GEMMs (bx < NBS) + embed16 conversion (bx >= NBS).
// ---------------------------------------------------------------------------
__global__ __launch_bounds__(128) void self_embed_kernel(
    const float* __restrict__ agg_table, const float* __restrict__ ff_table,
    const int* __restrict__ nodes, const int* __restrict__ unique_ids,
    const float* __restrict__ Wv_agg, const float* __restrict__ Wv_ff,
    const float* __restrict__ Wk,     const float* __restrict__ Wq)
{
    extern __shared__ unsigned smem[];
    const int bx = blockIdx.x;
    const int lane = threadIdx.x & 31;
    const int warp = threadIdx.x >> 5;

    if (bx >= NBS) {
        // embed16: 4 rows per block, warp per row
        int row = (bx - NBS) * 4 + warp;
        int uid = __ldg(unique_ids + row);
        float4 v = __ldcg((const float4*)(agg_table + (long)uid * DIN + lane * 4));
        __half2 h01 = __floats2half2_rn(v.x, v.y);
        __half2 h23 = __floats2half2_rn(v.z, v.w);
        *(uint2*)(g_embed_h + (long)row * DIN + lane * 4) =
            make_uint2(*(unsigned*)&h01, *(unsigned*)&h23);
        return;
    }

    // self GEMM job: 6 (grp,wsel) x 32 m-blocks of 64 rows
    int b = bx;
    int grp = b / 96;                // 0: agg, 1: ff
    int b2 = b % 96;
    int wsel = b2 / 32, mb = b2 % 32;
    const float* table = grp ? ff_table : agg_table;
    const float* W = (wsel == 0) ? (grp ? Wv_ff : Wv_agg) : (wsel == 1 ? Wk : Wq);
    float* out = grp ? g_ff_all : g_agg_all;
    const int row0 = mb * 64;
    const int col0 = wsel * 128;

    GemmCtx c; gemm_init(c, smem);

    // stage A: 16 gathered rows per warp
    int myidx = __ldg(nodes + row0 + c.wr0 + (lane & 15));
    #pragma unroll
    for (int e = 0; e < 16; e++) {
        int ridx = __shfl_sync(0xffffffffu, myidx, e);
        float4 x = __ldcg((const float4*)(table + (long)ridx * DIN + lane * 4));
        __half2 h01 = __floats2half2_rn(x.x, x.y);
        __half2 h23 = __floats2half2_rn(x.z, x.w);
        *(uint2*)(c.As + (c.wr0 + e) * LDA2 + lane * 2) =
            make_uint2(*(unsigned*)&h01, *(unsigned*)&h23);
    }
    gemm_stage_w(c, W);
    __syncthreads();

    float acc[16][4];
    gemm_main(c, acc);

    #pragma unroll
    for (int j = 0; j < 16; j++) {
        int col = col0 + j * 8 + 2 * c.tg;
        int r0g = row0 + c.wr0 + c.g;
        *(float2*)(out + (long)r0g * 384 + col) = make_float2(acc[j][0], acc[j][1]);
        *(float2*)(out + (long)(r0g + 8) * 384 + col) = make_float2(acc[j][2], acc[j][3]);
    }
}

// ---------------------------------------------------------------------------
// K2: aggregate — warp = (node, layer), fp16 embed rows, dedup + compact mean.
// ---------------------------------------------------------------------------
__global__ __launch_bounds__(256) void aggregate_kernel(
    const int* __restrict__ layer_idx, const int* __restrict__ col_idx)
{
    const int lane = threadIdx.x & 31;
    const int warp = threadIdx.x >> 5;          // 0..7
    const int n = blockIdx.x * 2 + (warp >> 2);
    const int m = warp & 3;

    int lay = __ldg(layer_idx + n * EPB + lane);
    int col = __ldg(col_idx + n * EPB + lane);
    int key = (lay << 15) | col;
    unsigned mm = __match_any_sync(0xffffffffu, key);
    bool valid = ((mm & ((1u << lane) - 1u)) == 0u);
    unsigned bits = __ballot_sync(0xffffffffu, valid && (lay == m));
    const int cm = __popc(bits);

    int pos = (int)__fns(bits, 0, lane + 1);
    int epos = (pos < 0 || pos > 31) ? 0 : pos;
    int slotcol = __shfl_sync(0xffffffffu, col, epos);

    float acc0 = 0.f, acc1 = 0.f, acc2 = 0.f, acc3 = 0.f;
    #pragma unroll
    for (int b = 0; b < 4; b++) {
        if (cm > 8 * b) {                        // warp-uniform
            uint2 v[8]; float wt[8];
            #pragma unroll
            for (int j = 0; j < 8; j++) {
                int slot = 8 * b + j;
                int ce = __shfl_sync(0xffffffffu, slotcol, slot);
                wt[j] = (slot < cm) ? 1.f : 0.f;
                v[j] = *(const uint2*)(g_embed_h + (long)ce * DIN + lane * 4);
            }
            #pragma unroll
            for (int j = 0; j < 8; j++) {
                float2 f01 = __half22float2(*(__half2*)&v[j].x);
                float2 f23 = __half22float2(*(__half2*)&v[j].y);
                acc0 = fmaf(f01.x, wt[j], acc0);
                acc1 = fmaf(f01.y, wt[j], acc1);
                acc2 = fmaf(f23.x, wt[j], acc2);
                acc3 = fmaf(f23.y, wt[j], acc3);
            }
        }
    }
    float inv = __fdividef(1.f, fmaxf((float)cm, 1.f));
    __half2 h01 = __floats2half2_rn(acc0 * inv, acc1 * inv);
    __half2 h23 = __floats2half2_rn(acc2 * inv, acc3 * inv);
    *(uint2*)(g_neigh_h + (long)(n * NMC + m) * DIN + lane * 4) =
        make_uint2(*(unsigned*)&h01, *(unsigned*)&h23);
}

// ---------------------------------------------------------------------------
// K3: neigh GEMM (m64 tile = 16 nodes) + fused finalize. 128 blocks.
// ---------------------------------------------------------------------------
__global__ __launch_bounds__(128) void neigh_fin_kernel(
    const float* __restrict__ Wv_agg, const float* __restrict__ mu_w,
    float* __restrict__ out)
{
    extern __shared__ unsigned smem[];
    const int bx = blockIdx.x;
    const int lane = threadIdx.x & 31;
    const int row0 = bx * 64;                 // neigh rows; nodes [bx*16, +16)

    GemmCtx c; gemm_init(c, smem);

    // stage A: contiguous fp16 neigh rows
    #pragma unroll
    for (int i = 0; i < 16; i++) {
        uint2 x = __ldcg((const uint2*)(g_neigh_h + (long)(row0 + c.wr0 + i) * DIN + lane * 4));
        *(uint2*)(c.As + (c.wr0 + i) * LDA2 + lane * 2) = x;
    }
    gemm_stage_w(c, Wv_agg);
    __syncthreads();

    float acc[16][4];
    gemm_main(c, acc);

    // spill acc to smem (aliased over As/Ws — all warps done with mainloop)
    __syncthreads();
    float* fin = (float*)smem;                // [64][LDF]
    #pragma unroll
    for (int j = 0; j < 16; j++) {
        int col = j * 8 + 2 * c.tg;
        *(float2*)(fin + (c.wr0 + c.g) * LDF + col) = make_float2(acc[j][0], acc[j][1]);
        *(float2*)(fin + (c.wr0 + 8 + c.g) * LDF + col) = make_float2(acc[j][2], acc[j][3]);
    }
    __syncwarp();

    // warp finalizes its own 4 nodes (local nodes 4*warp .. +3)
    float4 mu0 = *(const float4*)(mu_w + lane * 4);
    float4 mu1 = *(const float4*)(mu_w + DOUT + lane * 4);

    for (int nd = 0; nd < 4; nd++) {
        const int n = bx * 16 + c.warp * 4 + nd;
        const int lr0 = c.wr0 + nd * 4;       // local rows for node's 4 layers

        float4 nb[NMC];
        #pragma unroll
        for (int m = 0; m < NMC; m++)
            nb[m] = *(const float4*)(fin + (lr0 + m) * LDF + lane * 4);

        const float* ar = g_agg_all + (long)n * (3 * DOUT);
        const float* fr = g_ff_all  + (long)n * (3 * DOUT);
        float4 sa  = *(const float4*)(ar + lane * 4);
        float4 k0  = *(const float4*)(ar + DOUT + lane * 4);
        float4 q0  = *(const float4*)(ar + 2 * DOUT + lane * 4);
        float4 sff = *(const float4*)(fr + lane * 4);
        float4 k1  = *(const float4*)(fr + DOUT + lane * 4);
        float4 q1  = *(const float4*)(fr + 2 * DOUT + lane * 4);

        #define DOT4(a, b) ((a).x*(b).x + (a).y*(b).y + (a).z*(b).z + (a).w*(b).w)
        float p[14];
        p[0]  = DOT4(sa, sa);       p[1]  = DOT4(sa, mu0);
        p[2]  = DOT4(nb[0], nb[0]); p[3]  = DOT4(nb[0], mu1);
        p[4]  = DOT4(nb[1], nb[1]); p[5]  = DOT4(nb[1], mu1);
        p[6]  = DOT4(nb[2], nb[2]); p[7]  = DOT4(nb[2], mu1);
        p[8]  = DOT4(nb[3], nb[3]); p[9]  = DOT4(nb[3], mu1);
        p[10] = DOT4(k0, q0); p[11] = DOT4(k0, q1);
        p[12] = DOT4(k1, q0); p[13] = DOT4(k1, q1);

        #pragma unroll
        for (int o = 16; o > 0; o >>= 1)
            #pragma unroll
            for (int i = 0; i < 14; i++)
                p[i] += __shfl_xor_sync(0xffffffffu, p[i], o);

        float logit[NMC];
        #pragma unroll
        for (int m = 0; m < NMC; m++)
            logit[m] = (p[1] + p[3 + 2 * m]) *
                       __frsqrt_rn(fmaxf(p[0] + p[2 + 2 * m], 1e-24f));
        float mx = fmaxf(fmaxf(logit[0], logit[1]), fmaxf(logit[2], logit[3]));
        float ex[NMC], es = 0.f;
        #pragma unroll
        for (int m = 0; m < NMC; m++) { ex[m] = __expf(logit[m] - mx); es += ex[m]; }
        float ies = __fdividef(1.f, es);
        float4 nsum = make_float4(0.f, 0.f, 0.f, 0.f);
        #pragma unroll
        for (int m = 0; m < NMC; m++) {
            float cc = ex[m] * ies;
            nsum.x = fmaf(cc, nb[m].x, nsum.x); nsum.y = fmaf(cc, nb[m].y, nsum.y);
            nsum.z = fmaf(cc, nb[m].z, nsum.z); nsum.w = fmaf(cc, nb[m].w, nsum.w);
        }
        float4 va = make_float4(0.5f * (sa.x + nsum.x), 0.5f * (sa.y + nsum.y),
                                0.5f * (sa.z + nsum.z), 0.5f * (sa.w + nsum.w));

        float s00 = p[10] * (1.f / 128.f), s01 = p[11] * (1.f / 128.f);
        float s10 = p[12] * (1.f / 128.f), s11 = p[13] * (1.f / 128.f);
        float m0 = fmaxf(s00, s01), m1 = fmaxf(s10, s11);
        float e00 = __expf(s00 - m0), e01 = __expf(s01 - m0);
        float e10 = __expf(s10 - m1), e11 = __expf(s11 - m1);
        float i0 = __fdividef(1.f, e00 + e01);
        float i1 = __fdividef(1.f, e10 + e11);
        float w00 = e00 * i0, w01 = e01 * i0;
        float w10 = e10 * i1, w11 = e11 * i1;

        float4 o0, o1;
        #define FIN(comp) do { \
            float nv0 = w00 * va.comp + w01 * sff.comp; \
            float nv1 = w10 * va.comp + w11 * sff.comp; \
            float a0 = RES * va.comp  + (1.f - RES) * nv0; \
            float a1 = RES * sff.comp + (1.f - RES) * nv1; \
            o0.comp = (a0 > 0.f) ? a0 : (__expf(a0) - 1.f); \
            o1.comp = (a1 > 0.f) ? a1 : (__expf(a1) - 1.f); \
        } while (0)
        FIN(x); FIN(y); FIN(z); FIN(w);
        #undef FIN

        *(float4*)(out + (long)n * DOUT + lane * 4) = o0;
        *(float4*)(out + (long)NB * DOUT + (long)n * DOUT + lane * 4) = o1;
    }
}

// ---------------------------------------------------------------------------
extern "C" void kernel_launch(void* const* d_in, const int* in_sizes, int n_in,
                              void* d_out, int out_size)
{
    const int*   nodes      = (const int*)  d_in[0];
    const int*   unique_ids = (const int*)  d_in[1];
    // d_in[2] = row_idx: repeat(arange(B), 32) — implicit
    const int*   layer_idx  = (const int*)  d_in[3];
    const int*   col_idx    = (const int*)  d_in[4];
    const float* agg_table  = (const float*)d_in[5];
    const float* ff_table   = (const float*)d_in[6];
    const float* Wv_agg     = (const float*)d_in[7];
    const float* Wv_ff      = (const float*)d_in[8];
    const float* Wk         = (const float*)d_in[9];
    const float* Wq         = (const float*)d_in[10];
    const float* mu_w       = (const float*)d_in[11];
    float* out = (float*)d_out;

    const int smem_bytes = (64 * LDA2 + 128 * (LDWH / 2)) * (int)sizeof(unsigned);
    cudaFuncSetAttribute(self_embed_kernel,
                         cudaFuncAttributeMaxDynamicSharedMemorySize, smem_bytes);
    cudaFuncSetAttribute(neigh_fin_kernel,
                         cudaFuncAttributeMaxDynamicSharedMemorySize, smem_bytes);

    self_embed_kernel<<<NBS + NBE5, 128, smem_bytes>>>(
        agg_table, ff_table, nodes, unique_ids, Wv_agg, Wv_ff, Wk, Wq);

    aggregate_kernel<<<NB / 2, 256>>>(layer_idx, col_idx);

    neigh_fin_kernel<<<NB * NMC / 64, 128, smem_bytes>>>(Wv_agg, mu_w, out);
}

// round 13
// speedup vs baseline: 1.2423x; 1.2392x over previous
#include <cuda_runtime.h>
#include <cuda_fp16.h>
#include <math.h>

#define DIN   128
#define DOUT  128
#define NB    2048
#define NU    20000
#define NMC   4
#define EPB   32
#define RES   0.9f

#define NBE   157           // ceil(20000/128) blocks for embed GEMM
#define LDA2  68            // A smem row stride in half2 words
#define LDWH  136           // W smem row stride in halfs (68 half2 words)

// Scratch
__device__ __half g_embed_h[NU * DOUT];       // [20000,128] fp16 embed @ Wv_agg
__device__ float  g_agg_all[NB * 3 * DOUT];   // [2048,384] = self_agg | K0 | Q0
__device__ float  g_ff_all [NB * 3 * DOUT];   // [2048,384] = self_ff  | K1 | Q1

__device__ __forceinline__ void mma_f16(float* c, const unsigned* a,
                                        unsigned b0, unsigned b1) {
    asm volatile(
        "mma.sync.aligned.m16n8k16.row.col.f32.f16.f16.f32 "
        "{%0,%1,%2,%3}, {%4,%5,%6,%7}, {%8,%9}, {%0,%1,%2,%3};\n"
        : "+f"(c[0]), "+f"(c[1]), "+f"(c[2]), "+f"(c[3])
        : "r"(a[0]), "r"(a[1]), "r"(a[2]), "r"(a[3]), "r"(b0), "r"(b1));
}

// ---------------------------------------------------------------------------
// Gather-GEMM, fp16 mma (m16n8k16), fp32 accumulate. (R7 structure)
// Block: m128 x n128, K=128, 4 warps (warp = m32 x n128), 2 blocks/SM.
// Embed job (bx < NBE) writes fp16 output; self jobs write fp32.
// ---------------------------------------------------------------------------
__global__ __launch_bounds__(128, 2) void gemm_tc_kernel(
    const float* __restrict__ agg_table, const float* __restrict__ ff_table,
    const int* __restrict__ unique_ids,  const int* __restrict__ nodes,
    const float* __restrict__ Wv_agg, const float* __restrict__ Wv_ff,
    const float* __restrict__ Wk,     const float* __restrict__ Wq)
{
    extern __shared__ unsigned smem[];
    unsigned* As = smem;                    // [128][LDA2] half2 words
    unsigned* Ws = smem + 128 * LDA2;       // [128][LDWH/2] half2 words

    // job decode
    const float* table; const int* idx; const float* W; float* out;
    int M, ldout, col0, row0, embed_job;
    int bx = blockIdx.x;
    if (bx < NBE) {
        embed_job = 1;
        table = agg_table; idx = unique_ids; W = Wv_agg; out = nullptr;
        M = NU; ldout = DOUT; col0 = 0; row0 = bx * 128;
    } else {
        embed_job = 0;
        int b = bx - NBE;
        int grp = b / 48;            // 0: agg, 1: ff
        int b2 = b % 48;
        int wsel = b2 / 16, mb = b2 % 16;
        table = grp ? ff_table : agg_table;
        idx = nodes;
        W = (wsel == 0) ? (grp ? Wv_ff : Wv_agg) : (wsel == 1 ? Wk : Wq);
        out = grp ? g_ff_all : g_agg_all;
        M = NB; ldout = 3 * DOUT; col0 = wsel * 128; row0 = mb * 128;
    }

    const int lane = threadIdx.x & 31;
    const int warp = threadIdx.x >> 5;
    const int g  = lane >> 2;
    const int tg = lane & 3;
    const int wr0 = warp * 32;

    // prefetch this warp's 32 row indices
    int myrow = row0 + wr0 + lane;
    myrow = (myrow < M) ? myrow : (M - 1);
    const int myidx = __ldg(idx + myrow);

    // stage A rows first (long-latency gathers, independent addresses)
    #pragma unroll
    for (int e = 0; e < 32; e++) {
        int ridx = __shfl_sync(0xffffffffu, myidx, e);
        float4 x = __ldcg((const float4*)(table + (long)ridx * DIN + lane * 4));
        __half2 h01 = __floats2half2_rn(x.x, x.y);
        __half2 h23 = __floats2half2_rn(x.z, x.w);
        *(uint2*)(As + (wr0 + e) * LDA2 + lane * 2) =
            make_uint2(*(unsigned*)&h01, *(unsigned*)&h23);
    }

    // stage W rows [wr0, wr0+32)
    #pragma unroll
    for (int i = 0; i < 32; i++) {
        int row = wr0 + i;
        float4 v = *(const float4*)(W + row * 128 + lane * 4);
        __half2 h01 = __floats2half2_rn(v.x, v.y);
        __half2 h23 = __floats2half2_rn(v.z, v.w);
        *(uint2*)(Ws + row * (LDWH / 2) + lane * 2) =
            make_uint2(*(unsigned*)&h01, *(unsigned*)&h23);
    }
    __syncthreads();

    unsigned ws_s;
    {
        unsigned long long p;
        asm("cvta.to.shared.u64 %0, %1;" : "=l"(p) : "l"((const void*)Ws));
        ws_s = (unsigned)p;
    }

    float acc[2][16][4];
    #pragma unroll
    for (int mt = 0; mt < 2; mt++)
        #pragma unroll
        for (int j = 0; j < 16; j++)
            #pragma unroll
            for (int q = 0; q < 4; q++) acc[mt][j][q] = 0.f;

    const int lgrp = lane >> 3;
    const int lrow = lane & 7;
    const int kofs = (lgrp & 1) * 8 + lrow;
    const int nofs = (lgrp >> 1) * 8;

    #pragma unroll
    for (int kk = 0; kk < 8; kk++) {     // k16 chunks
        unsigned a[2][4];
        #pragma unroll
        for (int mt = 0; mt < 2; mt++) {
            const unsigned* ab = As + (wr0 + mt * 16) * LDA2 + kk * 8;
            a[mt][0] = ab[g * LDA2 + tg];
            a[mt][1] = ab[(g + 8) * LDA2 + tg];
            a[mt][2] = ab[g * LDA2 + 4 + tg];
            a[mt][3] = ab[(g + 8) * LDA2 + 4 + tg];
        }
        unsigned rowaddr = ws_s + ((kk * 16 + kofs) * LDWH + nofs) * 2;
        #pragma unroll
        for (int jj = 0; jj < 8; jj++) { // n16 chunks
            unsigned b0, b1, b2, b3;
            asm volatile(
                "ldmatrix.sync.aligned.m8n8.x4.trans.shared.b16 "
                "{%0,%1,%2,%3}, [%4];"
                : "=r"(b0), "=r"(b1), "=r"(b2), "=r"(b3)
                : "r"(rowaddr + jj * 32));
            mma_f16(acc[0][2 * jj],     a[0], b0, b1);
            mma_f16(acc[0][2 * jj + 1], a[0], b2, b3);
            mma_f16(acc[1][2 * jj],     a[1], b0, b1);
            mma_f16(acc[1][2 * jj + 1], a[1], b2, b3);
        }
    }

    // epilogue
    #pragma unroll
    for (int mt = 0; mt < 2; mt++) {
        int rbase = row0 + wr0 + mt * 16;
        #pragma unroll
        for (int j = 0; j < 16; j++) {
            int c = col0 + j * 8 + 2 * tg;
            int r0g = rbase + g;
            int r1g = rbase + 8 + g;
            if (embed_job) {
                if (r0g < M)
                    *(__half2*)(g_embed_h + (long)r0g * DOUT + c) =
                        __floats2half2_rn(acc[mt][j][0], acc[mt][j][1]);
                if (r1g < M)
                    *(__half2*)(g_embed_h + (long)r1g * DOUT + c) =
                        __floats2half2_rn(acc[mt][j][2], acc[mt][j][3]);
            } else {
                *(float2*)(out + (long)r0g * ldout + c) =
                    make_float2(acc[mt][j][0], acc[mt][j][1]);
                *(float2*)(out + (long)r1g * ldout + c) =
                    make_float2(acc[mt][j][2], acc[mt][j][3]);
            }
        }
    }
}

// ---------------------------------------------------------------------------
// Finalize: warp-per-node (4/block). fp16 embed gathers (uint2 = 4 dims/lane),
// 2 batches of 16 INDEPENDENT loads (MLP 16); selector shuffled in FMA phase.
// Fast-math epilogue.
// ---------------------------------------------------------------------------
#define NRED 14
__global__ __launch_bounds__(128, 3) void finalize_kernel(
    const int* __restrict__ layer_idx, const int* __restrict__ col_idx,
    const float* __restrict__ mu_w, float* __restrict__ out)
{
    const int lane = threadIdx.x & 31;
    const int warp = threadIdx.x >> 5;
    const int n = blockIdx.x * 4 + warp;

    // dedup (set semantics): first occurrence of (lay,col) within the warp
    int lay = layer_idx[n * EPB + lane];
    int col = col_idx[n * EPB + lane];
    int key = (lay << 15) | col;                 // col < 20000 < 2^15
    unsigned mm = __match_any_sync(0xffffffffu, key);
    bool valid = ((mm & ((1u << lane) - 1u)) == 0u);
    int vm = valid ? lay : -1;
    float cnt[NMC];
    cnt[0] = (float)__popc(__ballot_sync(0xffffffffu, valid && lay == 0));
    cnt[1] = (float)__popc(__ballot_sync(0xffffffffu, valid && lay == 1));
    cnt[2] = (float)__popc(__ballot_sync(0xffffffffu, valid && lay == 2));
    cnt[3] = (float)__popc(__ballot_sync(0xffffffffu, valid && lay == 3));

    // hoist self/K/Q/mu loads (overlap their latency with the gather phase)
    const float* ar = g_agg_all + (long)n * (3 * DOUT);
    const float* fr = g_ff_all  + (long)n * (3 * DOUT);
    float4 sa  = *(const float4*)(ar + lane * 4);
    float4 k0  = *(const float4*)(ar + DOUT + lane * 4);
    float4 q0  = *(const float4*)(ar + 2 * DOUT + lane * 4);
    float4 sff = *(const float4*)(fr + lane * 4);
    float4 k1  = *(const float4*)(fr + DOUT + lane * 4);
    float4 q1  = *(const float4*)(fr + 2 * DOUT + lane * 4);
    float4 mu0 = *(const float4*)(mu_w + lane * 4);
    float4 mu1 = *(const float4*)(mu_w + DOUT + lane * 4);

    // gather: 2 batches of 16 unconditional LDG.64 (fp16), selector FMA
    float4 nb[NMC];
    #pragma unroll
    for (int m = 0; m < NMC; m++) nb[m] = make_float4(0.f, 0.f, 0.f, 0.f);

    #pragma unroll
    for (int bb = 0; bb < 2; bb++) {
        uint2 v[16];
        #pragma unroll
        for (int e = 0; e < 16; e++) {
            int ce = __shfl_sync(0xffffffffu, col, bb * 16 + e);
            v[e] = __ldcg((const uint2*)(g_embed_h + (long)ce * DOUT + lane * 4));
        }
        #pragma unroll
        for (int e = 0; e < 16; e++) {
            int me = __shfl_sync(0xffffffffu, vm, bb * 16 + e);
            float2 f01 = __half22float2(*(__half2*)&v[e].x);
            float2 f23 = __half22float2(*(__half2*)&v[e].y);
            #pragma unroll
            for (int m = 0; m < NMC; m++) {
                float w = (me == m) ? 1.f : 0.f;
                nb[m].x = fmaf(f01.x, w, nb[m].x);
                nb[m].y = fmaf(f01.y, w, nb[m].y);
                nb[m].z = fmaf(f23.x, w, nb[m].z);
                nb[m].w = fmaf(f23.y, w, nb[m].w);
            }
        }
    }
    #pragma unroll
    for (int m = 0; m < NMC; m++) {
        float inv = __fdividef(1.f, fmaxf(cnt[m], 1.f));
        nb[m].x *= inv; nb[m].y *= inv; nb[m].z *= inv; nb[m].w *= inv;
    }

    #define DOT4(a, b) ((a).x*(b).x + (a).y*(b).y + (a).z*(b).z + (a).w*(b).w)
    float p[NRED];
    p[0]  = DOT4(sa, sa);       p[1]  = DOT4(sa, mu0);
    p[2]  = DOT4(nb[0], nb[0]); p[3]  = DOT4(nb[0], mu1);
    p[4]  = DOT4(nb[1], nb[1]); p[5]  = DOT4(nb[1], mu1);
    p[6]  = DOT4(nb[2], nb[2]); p[7]  = DOT4(nb[2], mu1);
    p[8]  = DOT4(nb[3], nb[3]); p[9]  = DOT4(nb[3], mu1);
    p[10] = DOT4(k0, q0); p[11] = DOT4(k0, q1);
    p[12] = DOT4(k1, q0); p[13] = DOT4(k1, q1);

    #pragma unroll
    for (int o = 16; o > 0; o >>= 1)
        #pragma unroll
        for (int i = 0; i < NRED; i++)
            p[i] += __shfl_xor_sync(0xffffffffu, p[i], o);

    // persona softmax (fast math)
    float logit[NMC];
    #pragma unroll
    for (int m = 0; m < NMC; m++)
        logit[m] = (p[1] + p[3 + 2 * m]) * __frsqrt_rn(fmaxf(p[0] + p[2 + 2 * m], 1e-24f));
    float mx = fmaxf(fmaxf(logit[0], logit[1]), fmaxf(logit[2], logit[3]));
    float ex[NMC], es = 0.f;
    #pragma unroll
    for (int m = 0; m < NMC; m++) { ex[m] = __expf(logit[m] - mx); es += ex[m]; }
    float ies = __fdividef(1.f, es);
    float4 nsum = make_float4(0.f, 0.f, 0.f, 0.f);
    #pragma unroll
    for (int m = 0; m < NMC; m++) {
        float c = ex[m] * ies;
        nsum.x = fmaf(c, nb[m].x, nsum.x); nsum.y = fmaf(c, nb[m].y, nsum.y);
        nsum.z = fmaf(c, nb[m].z, nsum.z); nsum.w = fmaf(c, nb[m].w, nsum.w);
    }
    float4 va = make_float4(0.5f * (sa.x + nsum.x), 0.5f * (sa.y + nsum.y),
                            0.5f * (sa.z + nsum.z), 0.5f * (sa.w + nsum.w));

    // 2x2 highway attention
    float s00 = p[10] * (1.f / 128.f), s01 = p[11] * (1.f / 128.f);
    float s10 = p[12] * (1.f / 128.f), s11 = p[13] * (1.f / 128.f);
    float m0 = fmaxf(s00, s01), m1 = fmaxf(s10, s11);
    float e00 = __expf(s00 - m0), e01 = __expf(s01 - m0);
    float e10 = __expf(s10 - m1), e11 = __expf(s11 - m1);
    float i0 = __fdividef(1.f, e00 + e01);
    float i1 = __fdividef(1.f, e10 + e11);
    float w00 = e00 * i0, w01 = e01 * i0;
    float w10 = e10 * i1, w11 = e11 * i1;

    float4 o0, o1;
    #define FIN(comp) do { \
        float nv0 = w00 * va.comp + w01 * sff.comp; \
        float nv1 = w10 * va.comp + w11 * sff.comp; \
        float a0 = RES * va.comp  + (1.f - RES) * nv0; \
        float a1 = RES * sff.comp + (1.f - RES) * nv1; \
        o0.comp = (a0 > 0.f) ? a0 : (__expf(a0) - 1.f); \
        o1.comp = (a1 > 0.f) ? a1 : (__expf(a1) - 1.f); \
    } while (0)
    FIN(x); FIN(y); FIN(z); FIN(w);

    *(float4*)(out + (long)n * DOUT + lane * 4) = o0;
    *(float4*)(out + (long)NB * DOUT + (long)n * DOUT + lane * 4) = o1;
}

// ---------------------------------------------------------------------------
extern "C" void kernel_launch(void* const* d_in, const int* in_sizes, int n_in,
                              void* d_out, int out_size)
{
    const int*   nodes      = (const int*)  d_in[0];
    const int*   unique_ids = (const int*)  d_in[1];
    // d_in[2] = row_idx: repeat(arange(B), 32) — implicit
    const int*   layer_idx  = (const int*)  d_in[3];
    const int*   col_idx    = (const int*)  d_in[4];
    const float* agg_table  = (const float*)d_in[5];
    const float* ff_table   = (const float*)d_in[6];
    const float* Wv_agg     = (const float*)d_in[7];
    const float* Wv_ff      = (const float*)d_in[8];
    const float* Wk         = (const float*)d_in[9];
    const float* Wq         = (const float*)d_in[10];
    const float* mu_w       = (const float*)d_in[11];
    float* out = (float*)d_out;

    const int smem_bytes = (128 * LDA2 + 128 * (LDWH / 2)) * (int)sizeof(unsigned);
    cudaFuncSetAttribute(gemm_tc_kernel,
                         cudaFuncAttributeMaxDynamicSharedMemorySize, smem_bytes);

    gemm_tc_kernel<<<NBE + 96, 128, smem_bytes>>>(
        agg_table, ff_table, unique_ids, nodes, Wv_agg, Wv_ff, Wk, Wq);

    finalize_kernel<<<NB / 4, 128>>>(layer_idx, col_idx, mu_w, out);
}

// round 14
// speedup vs baseline: 1.3621x; 1.0964x over previous
#include <cuda_runtime.h>
#include <cuda_fp16.h>
#include <math.h>

#define DIN   128
#define DOUT  128
#define NB    2048
#define NU    20000
#define NMC   4
#define EPB   32
#define RES   0.9f

#define NBE   157           // ceil(20000/128) blocks for embed GEMM
#define LDA2  68            // A smem row stride in half2 words
#define LDWH  136           // W smem row stride in halfs (68 half2 words)

// Scratch
__device__ __half g_embed_h[NU * DOUT];       // [20000,128] fp16 embed @ Wv_agg
__device__ float  g_agg_all[NB * 3 * DOUT];   // [2048,384] = self_agg | K0 | Q0
__device__ float  g_ff_all [NB * 3 * DOUT];   // [2048,384] = self_ff  | K1 | Q1

__device__ __forceinline__ void mma_f16(float* c, const unsigned* a,
                                        unsigned b0, unsigned b1) {
    asm volatile(
        "mma.sync.aligned.m16n8k16.row.col.f32.f16.f16.f32 "
        "{%0,%1,%2,%3}, {%4,%5,%6,%7}, {%8,%9}, {%0,%1,%2,%3};\n"
        : "+f"(c[0]), "+f"(c[1]), "+f"(c[2]), "+f"(c[3])
        : "r"(a[0]), "r"(a[1]), "r"(a[2]), "r"(a[3]), "r"(b0), "r"(b1));
}

// ---------------------------------------------------------------------------
// Gather-GEMM, fp16 mma (m16n8k16), fp32 accumulate.
// Block: m128 x n128, K=128, 4 warps (warp = m32 x n128), 2 blocks/SM.
// Embed job (bx < NBE) writes fp16 output; self jobs write fp32.
// ---------------------------------------------------------------------------
__global__ __launch_bounds__(128, 2) void gemm_tc_kernel(
    const float* __restrict__ agg_table, const float* __restrict__ ff_table,
    const int* __restrict__ unique_ids,  const int* __restrict__ nodes,
    const float* __restrict__ Wv_agg, const float* __restrict__ Wv_ff,
    const float* __restrict__ Wk,     const float* __restrict__ Wq)
{
    extern __shared__ unsigned smem[];
    unsigned* As = smem;                    // [128][LDA2] half2 words
    unsigned* Ws = smem + 128 * LDA2;       // [128][LDWH/2] half2 words

    // job decode
    const float* table; const int* idx; const float* W; float* out;
    int M, ldout, col0, row0, embed_job;
    int bx = blockIdx.x;
    if (bx < NBE) {
        embed_job = 1;
        table = agg_table; idx = unique_ids; W = Wv_agg; out = nullptr;
        M = NU; ldout = DOUT; col0 = 0; row0 = bx * 128;
    } else {
        embed_job = 0;
        int b = bx - NBE;
        int grp = b / 48;            // 0: agg, 1: ff
        int b2 = b % 48;
        int wsel = b2 / 16, mb = b2 % 16;
        table = grp ? ff_table : agg_table;
        idx = nodes;
        W = (wsel == 0) ? (grp ? Wv_ff : Wv_agg) : (wsel == 1 ? Wk : Wq);
        out = grp ? g_ff_all : g_agg_all;
        M = NB; ldout = 3 * DOUT; col0 = wsel * 128; row0 = mb * 128;
    }

    const int lane = threadIdx.x & 31;
    const int warp = threadIdx.x >> 5;
    const int g  = lane >> 2;
    const int tg = lane & 3;
    const int wr0 = warp * 32;

    // prefetch this warp's 32 row indices
    int myrow = row0 + wr0 + lane;
    myrow = (myrow < M) ? myrow : (M - 1);
    const int myidx = __ldg(idx + myrow);

    // stage A rows first (long-latency gathers, independent addresses)
    #pragma unroll
    for (int e = 0; e < 32; e++) {
        int ridx = __shfl_sync(0xffffffffu, myidx, e);
        float4 x = __ldcg((const float4*)(table + (long)ridx * DIN + lane * 4));
        __half2 h01 = __floats2half2_rn(x.x, x.y);
        __half2 h23 = __floats2half2_rn(x.z, x.w);
        *(uint2*)(As + (wr0 + e) * LDA2 + lane * 2) =
            make_uint2(*(unsigned*)&h01, *(unsigned*)&h23);
    }

    // stage W rows [wr0, wr0+32)
    #pragma unroll
    for (int i = 0; i < 32; i++) {
        int row = wr0 + i;
        float4 v = *(const float4*)(W + row * 128 + lane * 4);
        __half2 h01 = __floats2half2_rn(v.x, v.y);
        __half2 h23 = __floats2half2_rn(v.z, v.w);
        *(uint2*)(Ws + row * (LDWH / 2) + lane * 2) =
            make_uint2(*(unsigned*)&h01, *(unsigned*)&h23);
    }
    __syncthreads();

    unsigned ws_s;
    {
        unsigned long long p;
        asm("cvta.to.shared.u64 %0, %1;" : "=l"(p) : "l"((const void*)Ws));
        ws_s = (unsigned)p;
    }

    float acc[2][16][4];
    #pragma unroll
    for (int mt = 0; mt < 2; mt++)
        #pragma unroll
        for (int j = 0; j < 16; j++)
            #pragma unroll
            for (int q = 0; q < 4; q++) acc[mt][j][q] = 0.f;

    const int lgrp = lane >> 3;
    const int lrow = lane & 7;
    const int kofs = (lgrp & 1) * 8 + lrow;
    const int nofs = (lgrp >> 1) * 8;

    #pragma unroll
    for (int kk = 0; kk < 8; kk++) {     // k16 chunks
        unsigned a[2][4];
        #pragma unroll
        for (int mt = 0; mt < 2; mt++) {
            const unsigned* ab = As + (wr0 + mt * 16) * LDA2 + kk * 8;
            a[mt][0] = ab[g * LDA2 + tg];
            a[mt][1] = ab[(g + 8) * LDA2 + tg];
            a[mt][2] = ab[g * LDA2 + 4 + tg];
            a[mt][3] = ab[(g + 8) * LDA2 + 4 + tg];
        }
        unsigned rowaddr = ws_s + ((kk * 16 + kofs) * LDWH + nofs) * 2;
        #pragma unroll
        for (int jj = 0; jj < 8; jj++) { // n16 chunks
            unsigned b0, b1, b2, b3;
            asm volatile(
                "ldmatrix.sync.aligned.m8n8.x4.trans.shared.b16 "
                "{%0,%1,%2,%3}, [%4];"
                : "=r"(b0), "=r"(b1), "=r"(b2), "=r"(b3)
                : "r"(rowaddr + jj * 32));
            mma_f16(acc[0][2 * jj],     a[0], b0, b1);
            mma_f16(acc[0][2 * jj + 1], a[0], b2, b3);
            mma_f16(acc[1][2 * jj],     a[1], b0, b1);
            mma_f16(acc[1][2 * jj + 1], a[1], b2, b3);
        }
    }

    // epilogue
    #pragma unroll
    for (int mt = 0; mt < 2; mt++) {
        int rbase = row0 + wr0 + mt * 16;
        #pragma unroll
        for (int j = 0; j < 16; j++) {
            int c = col0 + j * 8 + 2 * tg;
            int r0g = rbase + g;
            int r1g = rbase + 8 + g;
            if (embed_job) {
                if (r0g < M)
                    *(__half2*)(g_embed_h + (long)r0g * DOUT + c) =
                        __floats2half2_rn(acc[mt][j][0], acc[mt][j][1]);
                if (r1g < M)
                    *(__half2*)(g_embed_h + (long)r1g * DOUT + c) =
                        __floats2half2_rn(acc[mt][j][2], acc[mt][j][3]);
            } else {
                *(float2*)(out + (long)r0g * ldout + c) =
                    make_float2(acc[mt][j][0], acc[mt][j][1]);
                *(float2*)(out + (long)r1g * ldout + c) =
                    make_float2(acc[mt][j][2], acc[mt][j][3]);
            }
        }
    }
}

// ---------------------------------------------------------------------------
// Finalize: warp-per-node (4/block). fp16 embed gathers, 4 batches of 8
// independent LDG.64; accumulation via WARP-UNIFORM 4-arm branch (4 FMAs/edge,
// duplicates skipped). Fast-math epilogue. Regs capped for 4 blocks/SM.
// ---------------------------------------------------------------------------
#define NRED 14
__global__ __launch_bounds__(128, 4) void finalize_kernel(
    const int* __restrict__ layer_idx, const int* __restrict__ col_idx,
    const float* __restrict__ mu_w, float* __restrict__ out)
{
    const int lane = threadIdx.x & 31;
    const int warp = threadIdx.x >> 5;
    const int n = blockIdx.x * 4 + warp;

    // dedup (set semantics): first occurrence of (lay,col) within the warp
    int lay = layer_idx[n * EPB + lane];
    int col = col_idx[n * EPB + lane];
    int key = (lay << 15) | col;                 // col < 20000 < 2^15
    unsigned mm = __match_any_sync(0xffffffffu, key);
    bool valid = ((mm & ((1u << lane) - 1u)) == 0u);
    int vm = valid ? lay : -1;
    float cnt[NMC];
    cnt[0] = (float)__popc(__ballot_sync(0xffffffffu, valid && lay == 0));
    cnt[1] = (float)__popc(__ballot_sync(0xffffffffu, valid && lay == 1));
    cnt[2] = (float)__popc(__ballot_sync(0xffffffffu, valid && lay == 2));
    cnt[3] = (float)__popc(__ballot_sync(0xffffffffu, valid && lay == 3));

    // gather: 4 batches of 8 independent LDG.64 (fp16 rows), uniform-branch FMA
    float4 nb[NMC];
    #pragma unroll
    for (int m = 0; m < NMC; m++) nb[m] = make_float4(0.f, 0.f, 0.f, 0.f);

    #pragma unroll
    for (int bb = 0; bb < 4; bb++) {
        uint2 v[8];
        #pragma unroll
        for (int e = 0; e < 8; e++) {
            int ce = __shfl_sync(0xffffffffu, col, bb * 8 + e);
            v[e] = __ldcg((const uint2*)(g_embed_h + (long)ce * DOUT + lane * 4));
        }
        #pragma unroll
        for (int e = 0; e < 8; e++) {
            int me = __shfl_sync(0xffffffffu, vm, bb * 8 + e);  // warp-uniform
            if (me >= 0) {                                      // skip duplicates
                float2 f01 = __half22float2(*(__half2*)&v[e].x);
                float2 f23 = __half22float2(*(__half2*)&v[e].y);
                if (me == 0) {
                    nb[0].x += f01.x; nb[0].y += f01.y; nb[0].z += f23.x; nb[0].w += f23.y;
                } else if (me == 1) {
                    nb[1].x += f01.x; nb[1].y += f01.y; nb[1].z += f23.x; nb[1].w += f23.y;
                } else if (me == 2) {
                    nb[2].x += f01.x; nb[2].y += f01.y; nb[2].z += f23.x; nb[2].w += f23.y;
                } else {
                    nb[3].x += f01.x; nb[3].y += f01.y; nb[3].z += f23.x; nb[3].w += f23.y;
                }
            }
        }
    }
    #pragma unroll
    for (int m = 0; m < NMC; m++) {
        float inv = __fdividef(1.f, fmaxf(cnt[m], 1.f));
        nb[m].x *= inv; nb[m].y *= inv; nb[m].z *= inv; nb[m].w *= inv;
    }

    // epilogue inputs
    const float* ar = g_agg_all + (long)n * (3 * DOUT);
    const float* fr = g_ff_all  + (long)n * (3 * DOUT);
    float4 sa  = *(const float4*)(ar + lane * 4);
    float4 k0  = *(const float4*)(ar + DOUT + lane * 4);
    float4 q0  = *(const float4*)(ar + 2 * DOUT + lane * 4);
    float4 sff = *(const float4*)(fr + lane * 4);
    float4 k1  = *(const float4*)(fr + DOUT + lane * 4);
    float4 q1  = *(const float4*)(fr + 2 * DOUT + lane * 4);
    float4 mu0 = *(const float4*)(mu_w + lane * 4);
    float4 mu1 = *(const float4*)(mu_w + DOUT + lane * 4);

    #define DOT4(a, b) ((a).x*(b).x + (a).y*(b).y + (a).z*(b).z + (a).w*(b).w)
    float p[NRED];
    p[0]  = DOT4(sa, sa);       p[1]  = DOT4(sa, mu0);
    p[2]  = DOT4(nb[0], nb[0]); p[3]  = DOT4(nb[0], mu1);
    p[4]  = DOT4(nb[1], nb[1]); p[5]  = DOT4(nb[1], mu1);
    p[6]  = DOT4(nb[2], nb[2]); p[7]  = DOT4(nb[2], mu1);
    p[8]  = DOT4(nb[3], nb[3]); p[9]  = DOT4(nb[3], mu1);
    p[10] = DOT4(k0, q0); p[11] = DOT4(k0, q1);
    p[12] = DOT4(k1, q0); p[13] = DOT4(k1, q1);

    #pragma unroll
    for (int o = 16; o > 0; o >>= 1)
        #pragma unroll
        for (int i = 0; i < NRED; i++)
            p[i] += __shfl_xor_sync(0xffffffffu, p[i], o);

    // persona softmax (fast math)
    float logit[NMC];
    #pragma unroll
    for (int m = 0; m < NMC; m++)
        logit[m] = (p[1] + p[3 + 2 * m]) * __frsqrt_rn(fmaxf(p[0] + p[2 + 2 * m], 1e-24f));
    float mx = fmaxf(fmaxf(logit[0], logit[1]), fmaxf(logit[2], logit[3]));
    float ex[NMC], es = 0.f;
    #pragma unroll
    for (int m = 0; m < NMC; m++) { ex[m] = __expf(logit[m] - mx); es += ex[m]; }
    float ies = __fdividef(1.f, es);
    float4 nsum = make_float4(0.f, 0.f, 0.f, 0.f);
    #pragma unroll
    for (int m = 0; m < NMC; m++) {
        float c = ex[m] * ies;
        nsum.x = fmaf(c, nb[m].x, nsum.x); nsum.y = fmaf(c, nb[m].y, nsum.y);
        nsum.z = fmaf(c, nb[m].z, nsum.z); nsum.w = fmaf(c, nb[m].w, nsum.w);
    }
    float4 va = make_float4(0.5f * (sa.x + nsum.x), 0.5f * (sa.y + nsum.y),
                            0.5f * (sa.z + nsum.z), 0.5f * (sa.w + nsum.w));

    // 2x2 highway attention
    float s00 = p[10] * (1.f / 128.f), s01 = p[11] * (1.f / 128.f);
    float s10 = p[12] * (1.f / 128.f), s11 = p[13] * (1.f / 128.f);
    float m0 = fmaxf(s00, s01), m1 = fmaxf(s10, s11);
    float e00 = __expf(s00 - m0), e01 = __expf(s01 - m0);
    float e10 = __expf(s10 - m1), e11 = __expf(s11 - m1);
    float i0 = __fdividef(1.f, e00 + e01);
    float i1 = __fdividef(1.f, e10 + e11);
    float w00 = e00 * i0, w01 = e01 * i0;
    float w10 = e10 * i1, w11 = e11 * i1;

    float4 o0, o1;
    #define FIN(comp) do { \
        float nv0 = w00 * va.comp + w01 * sff.comp; \
        float nv1 = w10 * va.comp + w11 * sff.comp; \
        float a0 = RES * va.comp  + (1.f - RES) * nv0; \
        float a1 = RES * sff.comp + (1.f - RES) * nv1; \
        o0.comp = (a0 > 0.f) ? a0 : (__expf(a0) - 1.f); \
        o1.comp = (a1 > 0.f) ? a1 : (__expf(a1) - 1.f); \
    } while (0)
    FIN(x); FIN(y); FIN(z); FIN(w);

    *(float4*)(out + (long)n * DOUT + lane * 4) = o0;
    *(float4*)(out + (long)NB * DOUT + (long)n * DOUT + lane * 4) = o1;
}

// ---------------------------------------------------------------------------
extern "C" void kernel_launch(void* const* d_in, const int* in_sizes, int n_in,
                              void* d_out, int out_size)
{
    const int*   nodes      = (const int*)  d_in[0];
    const int*   unique_ids = (const int*)  d_in[1];
    // d_in[2] = row_idx: repeat(arange(B), 32) — implicit
    const int*   layer_idx  = (const int*)  d_in[3];
    const int*   col_idx    = (const int*)  d_in[4];
    const float* agg_table  = (const float*)d_in[5];
    const float* ff_table   = (const float*)d_in[6];
    const float* Wv_agg     = (const float*)d_in[7];
    const float* Wv_ff      = (const float*)d_in[8];
    const float* Wk         = (const float*)d_in[9];
    const float* Wq         = (const float*)d_in[10];
    const float* mu_w       = (const float*)d_in[11];
    float* out = (float*)d_out;

    const int smem_bytes = (128 * LDA2 + 128 * (LDWH / 2)) * (int)sizeof(unsigned);
    cudaFuncSetAttribute(gemm_tc_kernel,
                         cudaFuncAttributeMaxDynamicSharedMemorySize, smem_bytes);

    gemm_tc_kernel<<<NBE + 96, 128, smem_bytes>>>(
        agg_table, ff_table, unique_ids, nodes, Wv_agg, Wv_ff, Wk, Wq);

    finalize_kernel<<<NB / 4, 128>>>(layer_idx, col_idx, mu_w, out);
}